// round 10
// baseline (speedup 1.0000x reference)
#include <cuda_runtime.h>
#include <cstdint>

#define BATCH 32
#define TT 1024
#define DKK 64
#define QT 32
#define NTH 256

#define RES_FLOATS ((size_t)BATCH * TT * DKK)  // 2097152
#define MASK_FILL_F (-4294967296.0f)           // float32(-2^32+1)

typedef unsigned long long ull;

// 8 MB scratch: V^T stored [b][d][k]
__device__ float VT_dev[(size_t)BATCH * DKK * TT];

__device__ __forceinline__ ull fma2(ull a, ull b, ull c) {
    ull d;
    asm("fma.rn.f32x2 %0, %1, %2, %3;" : "=l"(d) : "l"(a), "l"(b), "l"(c));
    return d;
}
__device__ __forceinline__ float hadd2(ull v) {
    float lo, hi;
    asm("mov.b64 {%0, %1}, %2;" : "=f"(lo), "=f"(hi) : "l"(v));
    return lo + hi;
}

// ---------------- transpose V: V[b][k][d] -> VT[b][d][k] ----------------
__global__ void transposeV_kernel(const float* __restrict__ Vg)
{
    __shared__ float t[32][33];
    const int b  = blockIdx.z;
    const int k0 = blockIdx.x * 32;
    const int d0 = blockIdx.y * 32;
    const int x  = threadIdx.x;       // 0..31
    const int y  = threadIdx.y;       // 0..7
    const float* Vb = Vg + ((size_t)b * TT + k0) * DKK + d0;
    #pragma unroll
    for (int i = 0; i < 32; i += 8)
        t[y + i][x] = Vb[(size_t)(y + i) * DKK + x];
    __syncthreads();
    float* VTb = VT_dev + ((size_t)b * DKK + d0) * TT + k0;
    #pragma unroll
    for (int i = 0; i < 32; i += 8)
        VTb[(size_t)(y + i) * TT + x] = t[x][y + i];
}

// ---------------- main fused attention kernel ----------------
__global__ void __launch_bounds__(NTH, 4)
mha_kernel(const float* __restrict__ Kg,
           const float* __restrict__ Qg,
           const unsigned int* __restrict__ Mg,   // bool as 4-byte: nonzero == True
           const float* __restrict__ QMg,
           float* __restrict__ out)
{
    __shared__ float qs[QT * DKK];   // Q tile, natural [q][d]; reused as reduction buf in C

    const int tid = threadIdx.x;
    const int tx  = tid & 31, ty = tid >> 5;   // ty 0..7
    const int b   = blockIdx.x >> 5;
    const int qt  = blockIdx.x & 31;
    const int q0g = qt * QT;

    const float* Qb  = Qg + ((size_t)b * TT + q0g) * DKK;
    const float* Kb  = Kg + (size_t)b * TT * DKK;
    const float* VTb = VT_dev + (size_t)b * DKK * TT;
    float* attnG = out + RES_FLOATS + ((size_t)b * TT + q0g) * (size_t)TT;  // [32][1024]

    // ---- stage Q natural layout ----
    for (int idx = tid; idx < QT * DKK; idx += NTH)
        qs[idx] = Qb[idx];
    __syncthreads();

    // ========== Phase A: scores = (Q K^T)/8 -> gmem attn, FFMA2 over d ==========
    // warp = (q-half) x (k-quarter); lanes 4(q-grp) x 8(k-grp); thread 4q x 4k.
    {
        const int qh = ty & 1, kq = ty >> 1;
        const int qb = qh * 16 + (tx >> 3) * 4;   // 0..28
        const int kl = (tx & 7) * 4;              // 0..28 in 32-window

        for (int win = 0; win < 8; ++win) {
            const int k0 = kq * 32 + win * 128 + kl;
            ull acc2[4][4] = {};
            #pragma unroll 4
            for (int dq = 0; dq < DKK; dq += 4) {
                ulonglong2 qp[4], kp[4];
                #pragma unroll
                for (int r = 0; r < 4; ++r)
                    qp[r] = *(const ulonglong2*)&qs[(qb + r) * DKK + dq];
                #pragma unroll
                for (int i = 0; i < 4; ++i)
                    kp[i] = *(const ulonglong2*)&Kb[(size_t)(k0 + i) * DKK + dq];
                #pragma unroll
                for (int r = 0; r < 4; ++r)
                    #pragma unroll
                    for (int i = 0; i < 4; ++i) {
                        acc2[r][i] = fma2(qp[r].x, kp[i].x, acc2[r][i]);
                        acc2[r][i] = fma2(qp[r].y, kp[i].y, acc2[r][i]);
                    }
            }
            #pragma unroll
            for (int r = 0; r < 4; ++r) {
                float4 w = make_float4(hadd2(acc2[r][0]) * 0.125f,
                                       hadd2(acc2[r][1]) * 0.125f,
                                       hadd2(acc2[r][2]) * 0.125f,
                                       hadd2(acc2[r][3]) * 0.125f);
                *(float4*)&attnG[(size_t)(qb + r) * TT + k0] = w;
            }
        }
    }
    __syncthreads();

    // ========== Phase B: mask + softmax + query_mask (registers) ==========
    {
        #pragma unroll
        for (int r = 0; r < 4; ++r) {
            const int q  = ty * 4 + r;
            const int qg = q0g + q;
            float4* srow = (float4*)(attnG + (size_t)q * TT);
            const uint4* mrow = (const uint4*)(Mg + ((size_t)b * TT + qg) * (size_t)TT);

            float4 s[8];
            float mx = -3.402823466e38f;
            #pragma unroll
            for (int it = 0; it < 8; ++it) {
                const int k4 = tx + it * 32;
                uint4 m = mrow[k4];
                s[it] = srow[k4];
                if (m.x) s[it].x = MASK_FILL_F;
                if (m.y) s[it].y = MASK_FILL_F;
                if (m.z) s[it].z = MASK_FILL_F;
                if (m.w) s[it].w = MASK_FILL_F;
                mx = fmaxf(mx, fmaxf(fmaxf(s[it].x, s[it].y), fmaxf(s[it].z, s[it].w)));
            }
            #pragma unroll
            for (int o = 16; o; o >>= 1) mx = fmaxf(mx, __shfl_xor_sync(0xffffffffu, mx, o));

            float sum = 0.f;
            #pragma unroll
            for (int it = 0; it < 8; ++it) {
                s[it].x = __expf(s[it].x - mx); s[it].y = __expf(s[it].y - mx);
                s[it].z = __expf(s[it].z - mx); s[it].w = __expf(s[it].w - mx);
                sum += (s[it].x + s[it].y) + (s[it].z + s[it].w);
            }
            #pragma unroll
            for (int o = 16; o; o >>= 1) sum += __shfl_xor_sync(0xffffffffu, sum, o);

            const float inv = QMg[(size_t)b * TT + qg] / sum;
            #pragma unroll
            for (int it = 0; it < 8; ++it) {
                s[it].x *= inv; s[it].y *= inv; s[it].z *= inv; s[it].w *= inv;
                srow[tx + it * 32] = s[it];
            }
        }
    }
    __syncthreads();

    // ========== Phase C: result = attn @ V^T-layout, FFMA2 over k ==========
    // warp = (q-half) x (d-half) x (k-half); lanes 4(q-grp) x 8(d-grp); thread 4q x 4d.
    {
        const int qh = ty & 1, dh = (ty >> 1) & 1, kh = ty >> 2;
        const int qb = qh * 16 + (tx >> 3) * 4;
        const int dl = dh * 32 + (tx & 7) * 4;

        ull acc2[4][4] = {};
        const int kbeg = kh * 512;
        #pragma unroll 4
        for (int k = kbeg; k < kbeg + 512; k += 4) {
            ulonglong2 ap[4], vp[4];
            #pragma unroll
            for (int r = 0; r < 4; ++r)
                ap[r] = *(const ulonglong2*)&attnG[(size_t)(qb + r) * TT + k];
            #pragma unroll
            for (int i = 0; i < 4; ++i)
                vp[i] = *(const ulonglong2*)&VTb[(size_t)(dl + i) * TT + k];
            #pragma unroll
            for (int r = 0; r < 4; ++r)
                #pragma unroll
                for (int i = 0; i < 4; ++i) {
                    acc2[r][i] = fma2(ap[r].x, vp[i].x, acc2[r][i]);
                    acc2[r][i] = fma2(ap[r].y, vp[i].y, acc2[r][i]);
                }
        }

        float acc[4][4];
        #pragma unroll
        for (int r = 0; r < 4; ++r)
            #pragma unroll
            for (int i = 0; i < 4; ++i)
                acc[r][i] = hadd2(acc2[r][i]);

        // k-half partner reduction through smem (reuse qs: 2048 floats)
        __syncthreads();
        float* red = qs;
        const int t = tid & 127;     // partner index (same qh,dh,qb,dl)
        if (kh == 1) {
            #pragma unroll
            for (int r = 0; r < 4; ++r)
                *(float4*)&red[t * 16 + r * 4] =
                    make_float4(acc[r][0], acc[r][1], acc[r][2], acc[r][3]);
        }
        __syncthreads();
        if (kh == 0) {
            #pragma unroll
            for (int r = 0; r < 4; ++r) {
                float4 p = *(float4*)&red[t * 16 + r * 4];
                float4 wv = make_float4(acc[r][0] + p.x, acc[r][1] + p.y,
                                        acc[r][2] + p.z, acc[r][3] + p.w);
                *(float4*)&out[((size_t)b * TT + q0g + qb + r) * DKK + dl] = wv;
            }
        }
    }
}

extern "C" void kernel_launch(void* const* d_in, const int* in_sizes, int n_in,
                              void* d_out, int out_size)
{
    (void)in_sizes; (void)n_in; (void)out_size;
    const float*        Kg  = (const float*)d_in[0];
    const float*        Vg  = (const float*)d_in[1];
    const float*        Qg  = (const float*)d_in[2];
    const unsigned int* Mg  = (const unsigned int*)d_in[3];
    const float*        QMg = (const float*)d_in[4];
    float*              out = (float*)d_out;

    dim3 tgrid(TT / 32, DKK / 32, BATCH);       // 32 x 2 x 32
    transposeV_kernel<<<tgrid, dim3(32, 8)>>>(Vg);

    dim3 grid(BATCH * (TT / QT));               // 1024 blocks
    mha_kernel<<<grid, NTH>>>(Kg, Qg, Mg, QMg, out);
}

// round 13
// speedup vs baseline: 3.8000x; 3.8000x over previous
#include <cuda_runtime.h>
#include <cstdint>

#define BATCH 32
#define TT 1024
#define DKK 64
#define QT 32
#define NTH 256

#define RES_FLOATS ((size_t)BATCH * TT * DKK)  // 2097152
#define MASK_FILL_F (-4294967296.0f)           // float32(-2^32+1)

// per-row bank-offset swizzle (floats); rows differing by 4 land on distinct bank-quads
#define ROFF(r) ((((r) >> 2) & 7) * 4)
// VT row address: two 32-row halves (4256 floats each) so the ROFF wrap at row 32
// cannot overlap row 31 (round-11 bug). 4256 % 32 == 0 -> bank pattern unchanged.
#define VROW(d) ((((d) >> 5) * 4256) + (((d) & 31) * 132) + ROFF(d))

// SMEM layout (floats), union of phases:
//  Phase A: K_s [128][68] at 0 (8704), Q_s rows 0..31 stride 68+ROFF at 8704 (2204)
//  Phase C: VTs two halves at 0 (2*4256=8512), ATs rows 0..31 stride 132+ROFF at 8512 (4256)
#define KS_OFF   0
#define QS_OFF   8704
#define ATS_OFF  8512
#define SMEM_FLOATS 12768
#define SMEM_BYTES  (SMEM_FLOATS * 4)   // 51072 -> 4 CTAs/SM

typedef unsigned long long ull;

// 8 MB scratch: V^T stored [b][d][k]
__device__ float VT_dev[(size_t)BATCH * DKK * TT];

__device__ __forceinline__ ull fma2(ull a, ull b, ull c) {
    ull d;
    asm("fma.rn.f32x2 %0, %1, %2, %3;" : "=l"(d) : "l"(a), "l"(b), "l"(c));
    return d;
}
__device__ __forceinline__ float hadd2(ull v) {
    float lo, hi;
    asm("mov.b64 {%0, %1}, %2;" : "=f"(lo), "=f"(hi) : "l"(v));
    return lo + hi;
}

// ---------------- transpose V: V[b][k][d] -> VT[b][d][k] ----------------
__global__ void transposeV_kernel(const float* __restrict__ Vg)
{
    __shared__ float t[32][33];
    const int b  = blockIdx.z;
    const int k0 = blockIdx.x * 32;
    const int d0 = blockIdx.y * 32;
    const int x  = threadIdx.x;       // 0..31
    const int y  = threadIdx.y;       // 0..7
    const float* Vb = Vg + ((size_t)b * TT + k0) * DKK + d0;
    #pragma unroll
    for (int i = 0; i < 32; i += 8)
        t[y + i][x] = Vb[(size_t)(y + i) * DKK + x];
    __syncthreads();
    float* VTb = VT_dev + ((size_t)b * DKK + d0) * TT + k0;
    #pragma unroll
    for (int i = 0; i < 32; i += 8)
        VTb[(size_t)(y + i) * TT + x] = t[x][y + i];
}

// ---------------- main fused attention kernel ----------------
__global__ void __launch_bounds__(NTH, 4)
mha_kernel(const float* __restrict__ Kg,
           const float* __restrict__ Qg,
           const unsigned int* __restrict__ Mg,   // bool as 4-byte: nonzero == True
           const float* __restrict__ QMg,
           float* __restrict__ out)
{
    extern __shared__ float sm[];

    const int tid = threadIdx.x;
    const int tx  = tid & 31, ty = tid >> 5;   // ty 0..7
    const int b   = blockIdx.x >> 5;
    const int qt  = blockIdx.x & 31;
    const int q0g = qt * QT;

    const float* Qb  = Qg + ((size_t)b * TT + q0g) * DKK;
    const float* Kb  = Kg + (size_t)b * TT * DKK;
    const float* VTb = VT_dev + (size_t)b * DKK * TT;
    float* attnG = out + RES_FLOATS + ((size_t)b * TT + q0g) * (size_t)TT;  // [32][1024]

    // ---- stage Q: sm[QS_OFF + q*68 + ROFF(q) + d] ----
    for (int idx = tid; idx < QT * DKK; idx += NTH) {
        int q = idx >> 6, d = idx & 63;
        sm[QS_OFF + q * 68 + ROFF(q) + d] = Qb[idx];
    }

    // ========== Phase A: scores = (Q K^T)/8 -> gmem attn, FFMA2 over d ==========
    // warp = (qh) x (kq quarter); lanes: 4 q-groups x 8 k-lanes; thread 4q x {k0+8i}.
    {
        const int qh = ty & 1, kq = ty >> 1;          // kq 0..3
        const int qb = qh * 16 + (tx >> 3) * 4;
        const int j  = tx & 7;
        float* Ks = sm + KS_OFF;
        const float* Qs = sm + QS_OFF;

        for (int win = 0; win < 8; ++win) {
            __syncthreads();
            // stage K chunk [128][64] natural layout, stride 68
            const float4* Kc4 = (const float4*)(Kb + (size_t)win * 128 * DKK);
            #pragma unroll
            for (int i = 0; i < 8; ++i) {
                int idx4 = tid + i * NTH;             // 0..2047
                int k = idx4 >> 4, d4 = (idx4 & 15) << 2;
                *(float4*)&Ks[k * 68 + d4] = Kc4[idx4];
            }
            __syncthreads();

            ull acc2[4][4] = {};
            #pragma unroll 4
            for (int dq = 0; dq < DKK; dq += 4) {
                ulonglong2 qp[4], kp[4];
                #pragma unroll
                for (int r = 0; r < 4; ++r)
                    qp[r] = *(const ulonglong2*)&Qs[(qb + r) * 68 + ROFF(qb + r) + dq];
                #pragma unroll
                for (int i = 0; i < 4; ++i)
                    kp[i] = *(const ulonglong2*)&Ks[(kq * 32 + j + 8 * i) * 68 + dq];
                #pragma unroll
                for (int r = 0; r < 4; ++r)
                    #pragma unroll
                    for (int i = 0; i < 4; ++i) {
                        acc2[r][i] = fma2(qp[r].x, kp[i].x, acc2[r][i]);
                        acc2[r][i] = fma2(qp[r].y, kp[i].y, acc2[r][i]);
                    }
            }
            const int kg0 = win * 128 + kq * 32 + j;
            #pragma unroll
            for (int r = 0; r < 4; ++r)
                #pragma unroll
                for (int i = 0; i < 4; ++i)
                    attnG[(size_t)(qb + r) * TT + kg0 + 8 * i] = hadd2(acc2[r][i]) * 0.125f;
        }
    }
    __syncthreads();

    // ========== Phase B: mask + softmax + query_mask (registers) ==========
    {
        #pragma unroll
        for (int r = 0; r < 4; ++r) {
            const int q  = ty * 4 + r;
            const int qg = q0g + q;
            float4* srow = (float4*)(attnG + (size_t)q * TT);
            const uint4* mrow = (const uint4*)(Mg + ((size_t)b * TT + qg) * (size_t)TT);

            float4 s[8];
            float mx = -3.402823466e38f;
            #pragma unroll
            for (int it = 0; it < 8; ++it) {
                const int k4 = tx + it * 32;
                uint4 m = mrow[k4];
                s[it] = srow[k4];
                if (m.x) s[it].x = MASK_FILL_F;
                if (m.y) s[it].y = MASK_FILL_F;
                if (m.z) s[it].z = MASK_FILL_F;
                if (m.w) s[it].w = MASK_FILL_F;
                mx = fmaxf(mx, fmaxf(fmaxf(s[it].x, s[it].y), fmaxf(s[it].z, s[it].w)));
            }
            #pragma unroll
            for (int o = 16; o; o >>= 1) mx = fmaxf(mx, __shfl_xor_sync(0xffffffffu, mx, o));

            float sum = 0.f;
            #pragma unroll
            for (int it = 0; it < 8; ++it) {
                s[it].x = __expf(s[it].x - mx); s[it].y = __expf(s[it].y - mx);
                s[it].z = __expf(s[it].z - mx); s[it].w = __expf(s[it].w - mx);
                sum += (s[it].x + s[it].y) + (s[it].z + s[it].w);
            }
            #pragma unroll
            for (int o = 16; o; o >>= 1) sum += __shfl_xor_sync(0xffffffffu, sum, o);

            const float inv = QMg[(size_t)b * TT + qg] / sum;
            #pragma unroll
            for (int it = 0; it < 8; ++it) {
                s[it].x *= inv; s[it].y *= inv; s[it].z *= inv; s[it].w *= inv;
                srow[tx + it * 32] = s[it];
            }
        }
    }

    // ========== Phase C: result = attn @ V (VT layout), FFMA2 over k ==========
    // warp = qh x dh x kh; lanes: 4 q-groups x 8 d-groups; thread 4q x 4d.
    {
        const int qh = ty & 1, dh = (ty >> 1) & 1, kh = ty >> 2;
        const int qb = qh * 16 + (tx >> 3) * 4;
        const int dl = dh * 32 + (tx & 7) * 4;
        float* VTs = sm;
        float* ATs = sm + ATS_OFF;

        ull acc2[4][4] = {};
        for (int kb = 0; kb < 8; ++kb) {
            __syncthreads();
            // stage VT chunk [64][128] -> two-half layout, conflict-free banks
            #pragma unroll
            for (int i = 0; i < 8; ++i) {
                int idx4 = tid + i * NTH;             // 0..2047
                int d = idx4 >> 5, k4 = (idx4 & 31) << 2;
                float4 v = *(const float4*)&VTb[(size_t)d * TT + kb * 128 + k4];
                *(float4*)&VTs[VROW(d) + k4] = v;
            }
            // stage attn chunk [32][128] -> stride 132 + ROFF (rows 0..31, no wrap)
            #pragma unroll
            for (int i = 0; i < 4; ++i) {
                int idx4 = tid + i * NTH;             // 0..1023
                int q = idx4 >> 5, k4 = (idx4 & 31) << 2;
                float4 a = *(const float4*)&attnG[(size_t)q * TT + kb * 128 + k4];
                *(float4*)&ATs[q * 132 + ROFF(q) + k4] = a;
            }
            __syncthreads();

            const int kbeg = kh * 64;
            #pragma unroll 4
            for (int k = kbeg; k < kbeg + 64; k += 4) {
                ulonglong2 ap[4], vp[4];
                #pragma unroll
                for (int r = 0; r < 4; ++r)
                    ap[r] = *(const ulonglong2*)&ATs[(qb + r) * 132 + ROFF(qb + r) + k];
                #pragma unroll
                for (int i = 0; i < 4; ++i)
                    vp[i] = *(const ulonglong2*)&VTs[VROW(dl + i) + k];
                #pragma unroll
                for (int r = 0; r < 4; ++r)
                    #pragma unroll
                    for (int i = 0; i < 4; ++i) {
                        acc2[r][i] = fma2(ap[r].x, vp[i].x, acc2[r][i]);
                        acc2[r][i] = fma2(ap[r].y, vp[i].y, acc2[r][i]);
                    }
            }
        }

        float acc[4][4];
        #pragma unroll
        for (int r = 0; r < 4; ++r)
            #pragma unroll
            for (int i = 0; i < 4; ++i)
                acc[r][i] = hadd2(acc2[r][i]);

        // kh partner reduction through smem
        __syncthreads();
        float* red = sm;                 // 128 * 16 floats = 2048
        const int t = tid & 127;
        if (kh == 1) {
            #pragma unroll
            for (int r = 0; r < 4; ++r)
                *(float4*)&red[t * 16 + r * 4] =
                    make_float4(acc[r][0], acc[r][1], acc[r][2], acc[r][3]);
        }
        __syncthreads();
        if (kh == 0) {
            #pragma unroll
            for (int r = 0; r < 4; ++r) {
                float4 p = *(float4*)&red[t * 16 + r * 4];
                float4 wv = make_float4(acc[r][0] + p.x, acc[r][1] + p.y,
                                        acc[r][2] + p.z, acc[r][3] + p.w);
                *(float4*)&out[((size_t)b * TT + q0g + qb + r) * DKK + dl] = wv;
            }
        }
    }
}

extern "C" void kernel_launch(void* const* d_in, const int* in_sizes, int n_in,
                              void* d_out, int out_size)
{
    (void)in_sizes; (void)n_in; (void)out_size;
    const float*        Kg  = (const float*)d_in[0];
    const float*        Vg  = (const float*)d_in[1];
    const float*        Qg  = (const float*)d_in[2];
    const unsigned int* Mg  = (const unsigned int*)d_in[3];
    const float*        QMg = (const float*)d_in[4];
    float*              out = (float*)d_out;

    dim3 tgrid(TT / 32, DKK / 32, BATCH);       // 32 x 2 x 32
    transposeV_kernel<<<tgrid, dim3(32, 8)>>>(Vg);

    cudaFuncSetAttribute(mha_kernel, cudaFuncAttributeMaxDynamicSharedMemorySize, SMEM_BYTES);
    dim3 grid(BATCH * (TT / QT));               // 1024 blocks
    mha_kernel<<<grid, NTH, SMEM_BYTES>>>(Kg, Qg, Mg, QMg, out);
}